// round 1
// baseline (speedup 1.0000x reference)
#include <cuda_runtime.h>

// Problem shapes (fixed by the dataset)
constexpr int B  = 8;
constexpr int H  = 512, W  = 512;
constexpr int HO = 1024, WO = 1024;
constexpr int FP = 514;              // padded fixed-map dim: coords -1..512
constexpr int NPIX = B * HO * WO;    // 8388608 output pixels
constexpr int NFIX = B * FP * FP;    // 2113568 fixed-map entries

// Scratch: precomputed "fixed" depth map on padded domain [-1,512]^2 per batch.
// 8 * 514 * 514 * 4 B = 8.45 MB  (fits comfortably in L2)
__device__ float g_fix[NFIX];

// Pass 1: for every padded coord (y,x) in [-1,512]^2, compute the first-valid
// candidate among the 9 offsets in reference order:
//   (0,0), (-1,-1),(-1,0),(-1,1),(0,-1),(0,1),(1,-1),(1,0),(1,1)
// OOB candidates are invalid (Zeros padding); value==0 is invalid.
__global__ void __launch_bounds__(256) fix_kernel(const float* __restrict__ depth) {
    int idx = blockIdx.x * blockDim.x + threadIdx.x;
    if (idx >= NFIX) return;
    int b  = idx / (FP * FP);
    int r  = idx - b * (FP * FP);
    int py = r / FP;            // 0..513
    int px = r - py * FP;       // 0..513
    int y = py - 1;             // -1..512
    int x = px - 1;

    const float* img = depth + b * (H * W);

    const int dy[9] = {0, -1, -1, -1, 0, 0, 1, 1, 1};
    const int dx[9] = {0, -1,  0,  1,-1, 1,-1, 0, 1};

    float c[9];
#pragma unroll
    for (int k = 0; k < 9; k++) {
        int cy = y + dy[k];
        int cx = x + dx[k];
        bool inb = ((unsigned)cy < (unsigned)H) & ((unsigned)cx < (unsigned)W);
        c[k] = inb ? __ldg(img + cy * W + cx) : 0.0f;
    }
    // first valid in order == last write wins iterating in reverse
    float v = 0.0f;
#pragma unroll
    for (int k = 8; k >= 0; k--) {
        if (c[k] != 0.0f) v = c[k];
    }
    g_fix[idx] = v;
}

// Pass 2: per output pixel, unnormalize (align_corners=True), round to nearest
// (ties-to-even, matching jnp.round), then one gather from the fixed map.
// Processes 2 pixels per thread via a float4 grid load and float2 store.
__global__ void __launch_bounds__(256) sample_kernel(const float4* __restrict__ grid,
                                                     float2* __restrict__ out) {
    int t = blockIdx.x * blockDim.x + threadIdx.x;
    if (t >= NPIX / 2) return;

    float4 g = grid[t];
    int base = t * 2;
    int b = base >> 20;                       // HO*WO = 1<<20; pairs never span batches
    const float* fixp = g_fix + b * (FP * FP);

    float2 o;
    {
        // ((g+1)*0.5)*511 == round_fp32(g+1) * 255.5 (mul by 0.5 is exact)
        float xf = __fmul_rn(__fadd_rn(g.x, 1.0f), 255.5f);
        float yf = __fmul_rn(__fadd_rn(g.y, 1.0f), 255.5f);
        int ix = __float2int_rn(xf) + 1;      // shift into padded coords
        int iy = __float2int_rn(yf) + 1;
        bool inb = ((unsigned)ix < (unsigned)FP) & ((unsigned)iy < (unsigned)FP);
        o.x = inb ? __ldg(fixp + iy * FP + ix) : 0.0f;
    }
    {
        float xf = __fmul_rn(__fadd_rn(g.z, 1.0f), 255.5f);
        float yf = __fmul_rn(__fadd_rn(g.w, 1.0f), 255.5f);
        int ix = __float2int_rn(xf) + 1;
        int iy = __float2int_rn(yf) + 1;
        bool inb = ((unsigned)ix < (unsigned)FP) & ((unsigned)iy < (unsigned)FP);
        o.y = inb ? __ldg(fixp + iy * FP + ix) : 0.0f;
    }
    out[t] = o;
}

extern "C" void kernel_launch(void* const* d_in, const int* in_sizes, int n_in,
                              void* d_out, int out_size) {
    const float*  depth = (const float*)d_in[0];   // (B,1,H,W) f32
    const float4* grid  = (const float4*)d_in[1];  // (B,Ho,Wo,2) f32, read as float4 pairs
    float2*       out   = (float2*)d_out;          // (B,1,Ho,Wo) f32

    fix_kernel<<<(NFIX + 255) / 256, 256>>>(depth);
    sample_kernel<<<(NPIX / 2 + 255) / 256, 256>>>(grid, out);
}

// round 2
// speedup vs baseline: 1.2100x; 1.2100x over previous
#include <cuda_runtime.h>

// Problem shapes (fixed by the dataset)
constexpr int B  = 8;
constexpr int H  = 512, W  = 512;
constexpr int HO = 1024, WO = 1024;
constexpr int FPY = 514;             // padded rows: y coords -1..512
constexpr int FPX = 516;             // padded row stride (514 valid cols + 2 pad for float4)
constexpr int TPR = 129;             // threads per fix row (129*4 = 516)
constexpr int NPIX = B * HO * WO;    // 8388608 output pixels
constexpr int NFIXT = B * FPY * TPR; // fix-pass threads

// Scratch: precomputed "fixed" depth map, padded domain, float4-aligned rows.
// 8 * 514 * 516 * 4 B = 8.49 MB (L2-resident)
__device__ float4 g_fix4[B * FPY * (FPX / 4)];

// Load 6 input floats covering columns [px0-2, px0+3] of `row` (0 if OOB).
__device__ __forceinline__ void load_row6(const float* __restrict__ img, int row,
                                          int px0, float v[6]) {
    if ((unsigned)row >= (unsigned)H) {
        v[0] = v[1] = v[2] = v[3] = v[4] = v[5] = 0.0f;
        return;
    }
    const float* rp = img + row * W;
    if (px0 >= 4 && px0 <= 508) {
        // fast path: two aligned float4 loads cover cols px0-4..px0+3
        float4 a = *(const float4*)(rp + px0 - 4);
        float4 b = *(const float4*)(rp + px0);
        v[0] = a.z; v[1] = a.w;
        v[2] = b.x; v[3] = b.y; v[4] = b.z; v[5] = b.w;
    } else {
#pragma unroll
        for (int i = 0; i < 6; i++) {
            int c = px0 - 2 + i;
            v[i] = ((unsigned)c < (unsigned)W) ? __ldg(rp + c) : 0.0f;
        }
    }
}

// Pass 1: for every padded coord (y,x) in [-1,512]^2, pick the first valid
// (nonzero, in-bounds) candidate among the 9 offsets in reference order:
//   (0,0), (-1,-1),(-1,0),(-1,1),(0,-1),(0,1),(1,-1),(1,0),(1,1)
// Each thread computes 4 consecutive outputs in one row.
__global__ void __launch_bounds__(256) fix_kernel(const float* __restrict__ depth) {
    int idx = blockIdx.x * blockDim.x + threadIdx.x;
    if (idx >= NFIXT) return;
    int row = idx / TPR;            // global padded row id (b*FPY + py)
    int t   = idx - row * TPR;
    int b   = row / FPY;
    int py  = row - b * FPY;
    int px0 = t * 4;                // first padded col handled by this thread
    int y   = py - 1;               // padded y coord

    const float* img = depth + b * (H * W);

    float m1[6], r0[6], p1[6];
    load_row6(img, y - 1, px0, m1);
    load_row6(img, y,     px0, r0);
    load_row6(img, y + 1, px0, p1);

    float4 o;
    float* op = &o.x;
#pragma unroll
    for (int j = 0; j < 4; j++) {
        // output x = (px0+j) - 1; tap cols x-1..x+1 -> local indices j, j+1, j+2
        float c[9] = { r0[j + 1],                       // center
                       m1[j], m1[j + 1], m1[j + 2],     // row y-1
                       r0[j],            r0[j + 2],     // row y
                       p1[j], p1[j + 1], p1[j + 2] };   // row y+1
        float v = 0.0f;
#pragma unroll
        for (int k = 8; k >= 0; k--) {
            if (c[k] != 0.0f) v = c[k];                  // first-valid via reverse last-write
        }
        op[j] = v;
    }
    g_fix4[row * (FPX / 4) + t] = o;
}

__device__ __forceinline__ float samp(const float* __restrict__ fixp,
                                      float gx, float gy) {
    // ((g+1)*0.5)*(511) == round_fp32(g+1) * 255.5 exactly (mul by 0.5 is exact);
    // __float2int_rn = ties-to-even = jnp.round
    float xf = __fmul_rn(__fadd_rn(gx, 1.0f), 255.5f);
    float yf = __fmul_rn(__fadd_rn(gy, 1.0f), 255.5f);
    int ix = __float2int_rn(xf) + 1;   // padded coords
    int iy = __float2int_rn(yf) + 1;
    bool inb = ((unsigned)ix < 514u) & ((unsigned)iy < 514u);
    return inb ? __ldg(fixp + iy * FPX + ix) : 0.0f;
}

// Pass 2: one gather per output pixel, 4 pixels per thread.
__global__ void __launch_bounds__(256) sample_kernel(const float4* __restrict__ grid,
                                                     float4* __restrict__ out) {
    int t = blockIdx.x * blockDim.x + threadIdx.x;
    if (t >= NPIX / 4) return;

    float4 ga = __ldcs(grid + 2 * t);      // streaming: don't pollute L2
    float4 gb = __ldcs(grid + 2 * t + 1);

    int b = t >> 18;                       // (t*4) / (HO*WO); quads never span batches
    const float* fixp = (const float*)g_fix4 + b * (FPY * FPX);

    float4 o;
    o.x = samp(fixp, ga.x, ga.y);
    o.y = samp(fixp, ga.z, ga.w);
    o.z = samp(fixp, gb.x, gb.y);
    o.w = samp(fixp, gb.z, gb.w);
    __stcs(out + t, o);                    // streaming store
}

extern "C" void kernel_launch(void* const* d_in, const int* in_sizes, int n_in,
                              void* d_out, int out_size) {
    const float*  depth = (const float*)d_in[0];   // (B,1,H,W) f32
    const float4* grid  = (const float4*)d_in[1];  // (B,Ho,Wo,2) f32 as float4 pairs
    float4*       out   = (float4*)d_out;          // (B,1,Ho,Wo) f32 as float4

    fix_kernel<<<(NFIXT + 255) / 256, 256>>>(depth);
    sample_kernel<<<(NPIX / 4 + 255) / 256, 256>>>(grid, out);
}